// round 14
// baseline (speedup 1.0000x reference)
#include <cuda_runtime.h>
#include <cuda_bf16.h>

#define LDIM 4096
#define BDIM 32
#define CIN  64
#define ODIM 128
#define KDIM 9
#define CCHUNKS 2               // split-K chunks over channel dim
#define CPER   (CIN / CCHUNKS)  // 32 channels per chunk
#define OCHUNK 64               // outputs per main-kernel block (32 o-pairs)

typedef unsigned long long u64;

// Scratch (allocation-free rule: __device__ globals)
__device__ float g_part[CCHUNKS * BDIM * LDIM];  // partial channel sums, 1 MB
__device__ ulonglong2 g_wp2[(ODIM / 2) * 5];     // o-pair packed weights+bias
__device__ float g_evinv;                        // 1 / ||err_vector||

// Constant bank: per o-pair, 5x ulonglong2 =
//   {{w0[o0],w0[o1]},{w1..}} , ... , {{w8[o0],w8[o1]},{b[o0],b[o1]}}
// -> 5 uniform LDCU.128 per o-pair; each FFMA2 produces TWO output channels.
__constant__ ulonglong2 c_wp2[(ODIM / 2) * 5];   // 5 KB

// ---- packed f32x2 helpers ----
__device__ __forceinline__ u64 pack2(float lo, float hi) {
    u64 r; asm("mov.b64 %0, {%1,%2};" : "=l"(r) : "f"(lo), "f"(hi)); return r;
}
__device__ __forceinline__ u64 ffma2(u64 a, u64 b, u64 c) {
    u64 d; asm("fma.rn.f32x2 %0, %1, %2, %3;" : "=l"(d) : "l"(a), "l"(b), "l"(c));
    return d;
}
__device__ __forceinline__ float2 unpack2(u64 v) {
    float2 f; asm("mov.b64 {%0,%1}, %2;" : "=f"(f.x), "=f"(f.y) : "l"(v)); return f;
}

// ---------------------------------------------------------------------------
// Kernel A: split-K channel reduction (512 blocks x 128 thr) + prep (block 512)
// ---------------------------------------------------------------------------
__global__ __launch_bounds__(128) void reduce_prep_kernel(
    const float* __restrict__ x,
    const float* __restrict__ wc,
    const float* __restrict__ ev,
    const float* __restrict__ bias) {

    const int bx = blockIdx.x;
    const int t  = threadIdx.x;

    if (bx < BDIM * 16) {                      // 512 reduce blocks
        const int b   = bx >> 4;               // 0..31
        const int sub = bx & 15;
        const int lt  = sub >> 1;              // l-tile 0..7 (128 float4 each)
        const int cc  = sub & 1;               // channel chunk 0..1
        const int l4  = lt * 128 + t;          // 0..1023

        const float4* xp = reinterpret_cast<const float4*>(x) +
                           ((size_t)b * CIN + cc * CPER) * (LDIM / 4) + l4;
        float4 a0 = make_float4(0.f, 0.f, 0.f, 0.f);
        float4 a1 = make_float4(0.f, 0.f, 0.f, 0.f);
#pragma unroll 8
        for (int i = 0; i < CPER; i += 2) {
            float4 v0 = __ldg(xp + (i    ) * (LDIM / 4));
            float4 v1 = __ldg(xp + (i + 1) * (LDIM / 4));
            a0.x += v0.x; a0.y += v0.y; a0.z += v0.z; a0.w += v0.w;
            a1.x += v1.x; a1.y += v1.y; a1.z += v1.z; a1.w += v1.w;
        }
        a0.x += a1.x; a0.y += a1.y; a0.z += a1.z; a0.w += a1.w;
        reinterpret_cast<float4*>(g_part)[(cc * BDIM + b) * (LDIM / 4) + l4] = a0;
        return;
    }

    // ---- prep block (128 threads) ----
    __shared__ float red[128];
    __shared__ float s_wn[ODIM][10];           // normalized w rows + bias

    float ssq = 0.f;
    for (int i = t; i < LDIM; i += 128) { float v = ev[i]; ssq += v * v; }
    red[t] = ssq;
    __syncthreads();
    for (int s = 64; s > 0; s >>= 1) {
        if (t < s) red[t] += red[t + s];
        __syncthreads();
    }
    if (t == 0) g_evinv = rsqrtf(red[0]);

    // one thread per output channel: normalize row into smem
    {
        float w[KDIM];
        float n = 0.f;
#pragma unroll
        for (int k = 0; k < KDIM; ++k) { w[k] = wc[t * KDIM + k]; n += w[k] * w[k]; }
        float inv = rsqrtf(n);
#pragma unroll
        for (int k = 0; k < KDIM; ++k) s_wn[t][k] = w[k] * inv;
        s_wn[t][9] = bias[t];
    }
    __syncthreads();

    // threads 0..63 pack o-pair rows: 5x ulonglong2 per pair
    if (t < ODIM / 2) {
        const int o0 = 2 * t, o1 = 2 * t + 1;
#pragma unroll
        for (int p = 0; p < 5; ++p) {
            const int s0 = 2 * p, s1 = 2 * p + 1;  // s1=9 -> bias slot
            ulonglong2 v;
            v.x = pack2(s_wn[o0][s0], s_wn[o1][s0]);
            v.y = pack2(s_wn[o0][s1], s_wn[o1][s1]);
            g_wp2[t * 5 + p] = v;
        }
    }
}

// ---------------------------------------------------------------------------
// Kernel B: out[b,o,l] = ev[l]/||ev|| * sum_k w[o,k]*xs[b, idx[k,l]] + bias[o]
// grid: (8 l-tiles of 512, 32 b, 2 o-chunks of 64) = 512 blocks x 256 thr
// => 4096 warps. lpt=2; each FFMA2 covers an O-PAIR for one l. Gathered
// values packed {g,g} ONCE per (k,l); weights via 5 uniform LDCU.128/o-pair.
// Body per o-pair: 5 LDC + 18 FFMA2 + 2 STG.64 for 4 output elements.
// ---------------------------------------------------------------------------
__global__ __launch_bounds__(256, 4) void gmconv_main_kernel(
    const int*   __restrict__ idxm,
    const float* __restrict__ ev,
    float*       __restrict__ out) {

    __shared__ float s_xs[LDIM];                    // 16 KB (only smem)

    const int tile  = blockIdx.x;                   // 0..7
    const int b     = blockIdx.y;                   // 0..31
    const int obase = blockIdx.z * OCHUNK;          // 0, 64
    const int t     = threadIdx.x;

    // stage xs[b] = p0 + p1 (L2-resident partials)
    {
        float4* s4 = reinterpret_cast<float4*>(s_xs);
        const float4* g4 = reinterpret_cast<const float4*>(g_part);
#pragma unroll
        for (int i = t; i < LDIM / 4; i += 256) {
            float4 p0 = __ldg(&g4[(0 * BDIM + b) * (LDIM / 4) + i]);
            float4 p1 = __ldg(&g4[(1 * BDIM + b) * (LDIM / 4) + i]);
            s4[i] = make_float4(p0.x + p1.x, p0.y + p1.y,
                                p0.z + p1.z, p0.w + p1.w);
        }
    }
    __syncthreads();

    const int l = tile * 512 + t * 2;
    const float evinv = g_evinv;
    float2 e2 = __ldg(reinterpret_cast<const float2*>(ev + l));
    const float ex = e2.x * evinv, ey = e2.y * evinv;

    // gather 9 neighbor pairs; duplicate each scalar into a f32x2 ONCE
    u64 gg0[KDIM], gg1[KDIM];
#pragma unroll
    for (int k = 0; k < KDIM; ++k) {
        int2 id = __ldg(reinterpret_cast<const int2*>(idxm + k * LDIM + l));
        const float a = s_xs[id.x] * ex;
        const float c = s_xs[id.y] * ey;
        gg0[k] = pack2(a, a);
        gg1[k] = pack2(c, c);
    }

    const ulonglong2* wbase = &c_wp2[(obase >> 1) * 5];
    float* outp = out + ((size_t)b * ODIM + obase) * LDIM + l;

#pragma unroll 4
    for (int op = 0; op < OCHUNK / 2; ++op) {
        const ulonglong2 p0 = wbase[op * 5 + 0];   // {w0 pair},{w1 pair}
        const ulonglong2 p1 = wbase[op * 5 + 1];   // {w2},{w3}
        const ulonglong2 p2 = wbase[op * 5 + 2];   // {w4},{w5}
        const ulonglong2 p3 = wbase[op * 5 + 3];   // {w6},{w7}
        const ulonglong2 p4 = wbase[op * 5 + 4];   // {w8},{bias pair}

        u64 a0 = p4.y, a1 = p4.y;                  // {b[o0],b[o1]}
        a0 = ffma2(p0.x, gg0[0], a0);  a1 = ffma2(p0.x, gg1[0], a1);
        a0 = ffma2(p0.y, gg0[1], a0);  a1 = ffma2(p0.y, gg1[1], a1);
        a0 = ffma2(p1.x, gg0[2], a0);  a1 = ffma2(p1.x, gg1[2], a1);
        a0 = ffma2(p1.y, gg0[3], a0);  a1 = ffma2(p1.y, gg1[3], a1);
        a0 = ffma2(p2.x, gg0[4], a0);  a1 = ffma2(p2.x, gg1[4], a1);
        a0 = ffma2(p2.y, gg0[5], a0);  a1 = ffma2(p2.y, gg1[5], a1);
        a0 = ffma2(p3.x, gg0[6], a0);  a1 = ffma2(p3.x, gg1[6], a1);
        a0 = ffma2(p3.y, gg0[7], a0);  a1 = ffma2(p3.y, gg1[7], a1);
        a0 = ffma2(p4.x, gg0[8], a0);  a1 = ffma2(p4.x, gg1[8], a1);

        // a0 = {out[o0,l], out[o1,l]},  a1 = {out[o0,l+1], out[o1,l+1]}
        const float2 f0 = unpack2(a0);
        const float2 f1 = unpack2(a1);
        __stcs(reinterpret_cast<float2*>(outp + (size_t)(2 * op) * LDIM),
               make_float2(f0.x, f1.x));
        __stcs(reinterpret_cast<float2*>(outp + (size_t)(2 * op + 1) * LDIM),
               make_float2(f0.y, f1.y));
    }
}

// ---------------------------------------------------------------------------
extern "C" void kernel_launch(void* const* d_in, const int* in_sizes, int n_in,
                              void* d_out, int out_size) {
    const float* x    = nullptr;
    const float* wc   = nullptr;
    const float* ev   = nullptr;
    const float* bias = nullptr;
    const int*   idxm = nullptr;

    for (int i = 0; i < n_in; ++i) {
        switch (in_sizes[i]) {
            case BDIM * CIN * LDIM: x    = (const float*)d_in[i]; break;  // 8388608
            case ODIM * KDIM:       wc   = (const float*)d_in[i]; break;  // 1152
            case LDIM:              ev   = (const float*)d_in[i]; break;  // 4096
            case ODIM:              bias = (const float*)d_in[i]; break;  // 128
            case KDIM * LDIM:       idxm = (const int*)  d_in[i]; break;  // 36864
            default: break;
        }
    }

    float* out = (float*)d_out;

    reduce_prep_kernel<<<BDIM * 16 + 1, 128>>>(x, wc, ev, bias);

    // ONE graph-capturable D2D memcpy node: o-pair weights -> const bank
    void* wsrc = nullptr;
    cudaGetSymbolAddress(&wsrc, g_wp2);
    cudaMemcpyToSymbolAsync(c_wp2, wsrc, (ODIM / 2) * 5 * sizeof(ulonglong2), 0,
                            cudaMemcpyDeviceToDevice, 0);

    gmconv_main_kernel<<<dim3(8, BDIM, 2), 256>>>(idxm, ev, out);
}